// round 1
// baseline (speedup 1.0000x reference)
#include <cuda_runtime.h>
#include <math_constants.h>

// Problem constants
#define Bb  2
#define Ss  2048
#define Hh  1024
#define NHh 16
#define HDd 64

// Scratch (device globals — no allocations allowed in kernel_launch)
__device__ float g_Q [Bb * Ss * Hh];
__device__ float g_Kt[Bb * Ss * Hh];   // K pre-transposed: [(b*1024 + h*64 + d) * 2048 + s]
__device__ float g_V [Bb * Ss * Hh];
__device__ float g_C [Bb * Ss * Hh];   // attention context

// ---------------------------------------------------------------------------
// SIMT fp32 GEMM: C[M,N] = A[M,K] @ B[K,N], M=4096, N=K=1024.
// 128x128 tile, BK=8, 256 threads, 8x8 micro-tile.
// TRANSK=true writes the output transposed per-head for the attention kernel.
// ---------------------------------------------------------------------------
template <bool TRANSK>
__global__ __launch_bounds__(256)
void gemm128(const float* __restrict__ A, const float* __restrict__ Bw,
             float* __restrict__ C)
{
    constexpr int K = Hh;
    constexpr int N = Hh;
    __shared__ __align__(16) float As[8][128];
    __shared__ __align__(16) float Bs[8][128];

    const int tid = threadIdx.x;
    const int tr  = tid >> 4;        // 0..15 (row group of 8)
    const int tc  = tid & 15;        // 0..15 (col group of 8)
    const int rowBase = blockIdx.y * 128;
    const int colBase = blockIdx.x * 128;

    float acc[8][8];
#pragma unroll
    for (int i = 0; i < 8; i++)
#pragma unroll
        for (int j = 0; j < 8; j++) acc[i][j] = 0.f;

    const int arow = tid >> 1;           // 0..127
    const int acol = (tid & 1) * 4;      // 0 or 4
    const int brow = tid >> 5;           // 0..7
    const int bcol = (tid & 31) * 4;     // 0..124
    const float* Ag = A  + (size_t)(rowBase + arow) * K + acol;
    const float* Bg = Bw + (size_t)brow * N + colBase + bcol;

    for (int k0 = 0; k0 < K; k0 += 8) {
        float4 av = *(const float4*)(Ag + k0);
        float4 bv = *(const float4*)(Bg + (size_t)k0 * N);
        As[acol + 0][arow] = av.x;
        As[acol + 1][arow] = av.y;
        As[acol + 2][arow] = av.z;
        As[acol + 3][arow] = av.w;
        *(float4*)&Bs[brow][bcol] = bv;
        __syncthreads();
#pragma unroll
        for (int kk = 0; kk < 8; kk++) {
            float4 a0 = *(const float4*)&As[kk][tr * 8];
            float4 a1 = *(const float4*)&As[kk][tr * 8 + 4];
            float4 b0 = *(const float4*)&Bs[kk][tc * 8];
            float4 b1 = *(const float4*)&Bs[kk][tc * 8 + 4];
            float ra[8] = {a0.x, a0.y, a0.z, a0.w, a1.x, a1.y, a1.z, a1.w};
            float rb[8] = {b0.x, b0.y, b0.z, b0.w, b1.x, b1.y, b1.z, b1.w};
#pragma unroll
            for (int i = 0; i < 8; i++)
#pragma unroll
                for (int j = 0; j < 8; j++)
                    acc[i][j] = fmaf(ra[i], rb[j], acc[i][j]);
        }
        __syncthreads();
    }

    if (!TRANSK) {
#pragma unroll
        for (int i = 0; i < 8; i++) {
            int r = rowBase + tr * 8 + i;
            float* Cp = C + (size_t)r * N + colBase + tc * 8;
            *(float4*)Cp       = make_float4(acc[i][0], acc[i][1], acc[i][2], acc[i][3]);
            *(float4*)(Cp + 4) = make_float4(acc[i][4], acc[i][5], acc[i][6], acc[i][7]);
        }
    } else {
        // K^T layout: [(b*1024 + n) * 2048 + s], n = h*64 + d, m = b*2048 + s
#pragma unroll
        for (int j = 0; j < 8; j++) {
            int n = colBase + tc * 8 + j;
#pragma unroll
            for (int i = 0; i < 8; i++) {
                int m = rowBase + tr * 8 + i;
                int b = m >> 11;
                int s = m & 2047;
                C[((size_t)((b << 10) + n)) * Ss + s] = acc[i][j];
            }
        }
    }
}

// ---------------------------------------------------------------------------
// Flash-attention fp32: one CTA per (q-tile=64, head, batch). 128 threads.
// Each thread owns an 8(row) x 4(col) micro-tile for both S=QK^T and O=PV.
// Smem: Q [64][64] row-major (broadcast reads), K d-major [64][64] reused as
// P row-major [64][64], V [64][64] natural. Exactly 48 KB -> 4 CTAs/SM.
// ---------------------------------------------------------------------------
__global__ __launch_bounds__(128)
void attn_kernel(const float* __restrict__ Q, const float* __restrict__ Kt,
                 const float* __restrict__ V, const int* __restrict__ mask,
                 float* __restrict__ Ctx)
{
    __shared__ __align__(16) float Qs [64][64];
    __shared__ __align__(16) float KPs[64][64];  // K tile (d-major), then P tile
    __shared__ __align__(16) float Vs [64][64];

    const int tid = threadIdx.x;
    const int tx  = tid & 15;    // kv/d column group (4 wide)
    const int ty  = tid >> 4;    // q row group (8 tall)
    const int qt  = blockIdx.x;
    const int h   = blockIdx.y;
    const int b   = blockIdx.z;

    const float* Qg  = Q  + ((size_t)(b * Ss + qt * 64)) * Hh + h * HDd;
    const float* Ktg = Kt + ((size_t)(b * Hh + h * HDd)) * Ss;
    const float* Vg  = V  + ((size_t)(b * Ss)) * Hh + h * HDd;
    const int*   mrw = mask + b * Ss;

    // Load Q tile (row-major), coalesced float4
#pragma unroll
    for (int ii = 0; ii < 8; ii++) {
        int f = tid + 128 * ii;
        int r = f >> 4;
        int dg = (f & 15) << 2;
        *(float4*)&Qs[r][dg] = *(const float4*)(Qg + (size_t)r * Hh + dg);
    }

    float m_i[8], l_i[8], O[8][4];
#pragma unroll
    for (int i = 0; i < 8; i++) {
        m_i[i] = -CUDART_INF_F;
        l_i[i] = 0.f;
#pragma unroll
        for (int j = 0; j < 4; j++) O[i][j] = 0.f;
    }

    for (int kt = 0; kt < Ss / 64; kt++) {
        // Load K tile (d-major rows from pre-transposed K) and V tile (kv-major)
#pragma unroll
        for (int ii = 0; ii < 8; ii++) {
            int f = tid + 128 * ii;
            int r  = f >> 4;
            int cg = (f & 15) << 2;
            *(float4*)&KPs[r][cg] = *(const float4*)(Ktg + (size_t)r * Ss + kt * 64 + cg);
            *(float4*)&Vs [r][cg] = *(const float4*)(Vg + ((size_t)(kt * 64 + r)) * Hh + cg);
        }
        __syncthreads();

        // ---- S = Q @ K^T (accumulate over d, 4-wide vectorized) ----
        float Sa[8][4];
#pragma unroll
        for (int i = 0; i < 8; i++)
#pragma unroll
            for (int j = 0; j < 4; j++) Sa[i][j] = 0.f;

#pragma unroll 2
        for (int d0 = 0; d0 < 64; d0 += 4) {
            float4 k0 = *(const float4*)&KPs[d0 + 0][tx * 4];
            float4 k1 = *(const float4*)&KPs[d0 + 1][tx * 4];
            float4 k2 = *(const float4*)&KPs[d0 + 2][tx * 4];
            float4 k3 = *(const float4*)&KPs[d0 + 3][tx * 4];
#pragma unroll
            for (int i = 0; i < 8; i++) {
                float4 qv = *(const float4*)&Qs[ty * 8 + i][d0];
                Sa[i][0] = fmaf(qv.x, k0.x, Sa[i][0]);
                Sa[i][0] = fmaf(qv.y, k1.x, Sa[i][0]);
                Sa[i][0] = fmaf(qv.z, k2.x, Sa[i][0]);
                Sa[i][0] = fmaf(qv.w, k3.x, Sa[i][0]);
                Sa[i][1] = fmaf(qv.x, k0.y, Sa[i][1]);
                Sa[i][1] = fmaf(qv.y, k1.y, Sa[i][1]);
                Sa[i][1] = fmaf(qv.z, k2.y, Sa[i][1]);
                Sa[i][1] = fmaf(qv.w, k3.y, Sa[i][1]);
                Sa[i][2] = fmaf(qv.x, k0.z, Sa[i][2]);
                Sa[i][2] = fmaf(qv.y, k1.z, Sa[i][2]);
                Sa[i][2] = fmaf(qv.z, k2.z, Sa[i][2]);
                Sa[i][2] = fmaf(qv.w, k3.z, Sa[i][2]);
                Sa[i][3] = fmaf(qv.x, k0.w, Sa[i][3]);
                Sa[i][3] = fmaf(qv.y, k1.w, Sa[i][3]);
                Sa[i][3] = fmaf(qv.z, k2.w, Sa[i][3]);
                Sa[i][3] = fmaf(qv.w, k3.w, Sa[i][3]);
            }
        }

        // ---- scale, clip, mask, online softmax ----
        const int kb  = kt * 64 + tx * 4;
        const int mk0 = mrw[kb + 0];
        const int mk1 = mrw[kb + 1];
        const int mk2 = mrw[kb + 2];
        const int mk3 = mrw[kb + 3];

        float escale[8];
#pragma unroll
        for (int i = 0; i < 8; i++) {
            float s0 = fminf(fmaxf(Sa[i][0] * 0.125f, -10000.f), 10000.f);
            float s1 = fminf(fmaxf(Sa[i][1] * 0.125f, -10000.f), 10000.f);
            float s2 = fminf(fmaxf(Sa[i][2] * 0.125f, -10000.f), 10000.f);
            float s3 = fminf(fmaxf(Sa[i][3] * 0.125f, -10000.f), 10000.f);
            if (mk0 == 0) s0 = -CUDART_INF_F;
            if (mk1 == 0) s1 = -CUDART_INF_F;
            if (mk2 == 0) s2 = -CUDART_INF_F;
            if (mk3 == 0) s3 = -CUDART_INF_F;

            float tm = fmaxf(fmaxf(s0, s1), fmaxf(s2, s3));
#pragma unroll
            for (int o = 8; o >= 1; o >>= 1)
                tm = fmaxf(tm, __shfl_xor_sync(0xffffffffu, tm, o));
            float mn = fmaxf(m_i[i], tm);

            float p0 = __expf(s0 - mn);
            float p1 = __expf(s1 - mn);
            float p2 = __expf(s2 - mn);
            float p3 = __expf(s3 - mn);
            float ps = (p0 + p1) + (p2 + p3);
#pragma unroll
            for (int o = 8; o >= 1; o >>= 1)
                ps += __shfl_xor_sync(0xffffffffu, ps, o);

            escale[i] = __expf(m_i[i] - mn);
            l_i[i] = l_i[i] * escale[i] + ps;
            m_i[i] = mn;
            Sa[i][0] = p0; Sa[i][1] = p1; Sa[i][2] = p2; Sa[i][3] = p3;
        }

        __syncthreads();  // done reading K tile -> safe to overwrite with P
#pragma unroll
        for (int i = 0; i < 8; i++)
            *(float4*)&KPs[ty * 8 + i][tx * 4] =
                make_float4(Sa[i][0], Sa[i][1], Sa[i][2], Sa[i][3]);
        __syncthreads();

        // ---- O = O*escale + P @ V ----
#pragma unroll
        for (int i = 0; i < 8; i++) {
            O[i][0] *= escale[i];
            O[i][1] *= escale[i];
            O[i][2] *= escale[i];
            O[i][3] *= escale[i];
        }
#pragma unroll 2
        for (int c0 = 0; c0 < 64; c0 += 4) {
            float4 v0 = *(const float4*)&Vs[c0 + 0][tx * 4];
            float4 v1 = *(const float4*)&Vs[c0 + 1][tx * 4];
            float4 v2 = *(const float4*)&Vs[c0 + 2][tx * 4];
            float4 v3 = *(const float4*)&Vs[c0 + 3][tx * 4];
#pragma unroll
            for (int i = 0; i < 8; i++) {
                float4 p = *(const float4*)&KPs[ty * 8 + i][c0];
                O[i][0] = fmaf(p.x, v0.x, O[i][0]);
                O[i][0] = fmaf(p.y, v1.x, O[i][0]);
                O[i][0] = fmaf(p.z, v2.x, O[i][0]);
                O[i][0] = fmaf(p.w, v3.x, O[i][0]);
                O[i][1] = fmaf(p.x, v0.y, O[i][1]);
                O[i][1] = fmaf(p.y, v1.y, O[i][1]);
                O[i][1] = fmaf(p.z, v2.y, O[i][1]);
                O[i][1] = fmaf(p.w, v3.y, O[i][1]);
                O[i][2] = fmaf(p.x, v0.z, O[i][2]);
                O[i][2] = fmaf(p.y, v1.z, O[i][2]);
                O[i][2] = fmaf(p.z, v2.z, O[i][2]);
                O[i][2] = fmaf(p.w, v3.z, O[i][2]);
                O[i][3] = fmaf(p.x, v0.w, O[i][3]);
                O[i][3] = fmaf(p.y, v1.w, O[i][3]);
                O[i][3] = fmaf(p.z, v2.w, O[i][3]);
                O[i][3] = fmaf(p.w, v3.w, O[i][3]);
            }
        }
        __syncthreads();  // before next tile's loads overwrite KPs/Vs
    }

    // ---- epilogue: O /= l, write context ----
#pragma unroll
    for (int i = 0; i < 8; i++) {
        int q = qt * 64 + ty * 8 + i;
        float inv = 1.f / l_i[i];
        *(float4*)&Ctx[((size_t)(b * Ss + q)) * Hh + h * HDd + tx * 4] =
            make_float4(O[i][0] * inv, O[i][1] * inv, O[i][2] * inv, O[i][3] * inv);
    }
}

// ---------------------------------------------------------------------------
extern "C" void kernel_launch(void* const* d_in, const int* in_sizes, int n_in,
                              void* d_out, int out_size)
{
    const float* X    = (const float*)d_in[0];
    const int*   mask = (const int*)  d_in[1];
    const float* WQ   = (const float*)d_in[2];
    const float* WK   = (const float*)d_in[3];
    const float* WV   = (const float*)d_in[4];
    const float* WO   = (const float*)d_in[5];
    float* out = (float*)d_out;

    float *pQ, *pKt, *pV, *pC;
    cudaGetSymbolAddress((void**)&pQ,  g_Q);
    cudaGetSymbolAddress((void**)&pKt, g_Kt);
    cudaGetSymbolAddress((void**)&pV,  g_V);
    cudaGetSymbolAddress((void**)&pC,  g_C);

    dim3 gg(Hh / 128, (Bb * Ss) / 128);   // (8, 32)
    gemm128<false><<<gg, 256>>>(X, WQ, pQ);
    gemm128<true ><<<gg, 256>>>(X, WK, pKt);
    gemm128<false><<<gg, 256>>>(X, WV, pV);
    attn_kernel<<<dim3(Ss / 64, NHh, Bb), 128>>>(pQ, pKt, pV, mask, pC);
    gemm128<false><<<gg, 256>>>(pC, WO, out);

    (void)in_sizes; (void)n_in; (void)out_size;
}

// round 6
// speedup vs baseline: 5.6412x; 5.6412x over previous
#include <cuda_runtime.h>
#include <cuda_fp16.h>
#include <math_constants.h>
#include <stdint.h>

#define Bb  2
#define Ss  2048
#define Hh  1024
#define NHh 16
#define HDd 64
#define Mm  (Bb*Ss)    // 4096

// -------------------- scratch (device globals; no allocs allowed) ----------
__device__ __half g_Xh[Mm * Hh];
__device__ __half g_Wh[4][Hh * Hh];          // WQ, WK, WV, WO in fp16
__device__ __half g_Qh[Mm * Hh];
__device__ __half g_Kh[Mm * Hh];
__device__ __half g_Vh[Mm * Hh];
__device__ __half g_Ch[Mm * Hh];             // attention context (fp16)

// -------------------- PTX helpers ------------------------------------------
__device__ __forceinline__ uint32_t su32(const void* p) {
    return (uint32_t)__cvta_generic_to_shared(p);
}
__device__ __forceinline__ void ldm_x4(uint32_t a, uint32_t& r0, uint32_t& r1,
                                       uint32_t& r2, uint32_t& r3) {
    asm volatile("ldmatrix.sync.aligned.m8n8.x4.shared.b16 {%0,%1,%2,%3}, [%4];"
                 : "=r"(r0), "=r"(r1), "=r"(r2), "=r"(r3) : "r"(a));
}
__device__ __forceinline__ void ldm_x4t(uint32_t a, uint32_t& r0, uint32_t& r1,
                                        uint32_t& r2, uint32_t& r3) {
    asm volatile("ldmatrix.sync.aligned.m8n8.x4.trans.shared.b16 {%0,%1,%2,%3}, [%4];"
                 : "=r"(r0), "=r"(r1), "=r"(r2), "=r"(r3) : "r"(a));
}
__device__ __forceinline__ void mma16816(float* c, const uint32_t* a, const uint32_t* b) {
    asm volatile(
        "mma.sync.aligned.m16n8k16.row.col.f32.f16.f16.f32 "
        "{%0,%1,%2,%3}, {%4,%5,%6,%7}, {%8,%9}, {%0,%1,%2,%3};"
        : "+f"(c[0]), "+f"(c[1]), "+f"(c[2]), "+f"(c[3])
        : "r"(a[0]), "r"(a[1]), "r"(a[2]), "r"(a[3]), "r"(b[0]), "r"(b[1]));
}
#define CPA16(dst, src) asm volatile("cp.async.cg.shared.global [%0], [%1], 16;" :: "r"(dst), "l"(src))
#define CPCOMMIT()      asm volatile("cp.async.commit_group;")
#define CPWAIT0()       asm volatile("cp.async.wait_group 0;")

__device__ __forceinline__ uint32_t packh2(float a, float b) {
    __half2 h = __floats2half2_rn(a, b);   // .x = a (low = k even elem)
    return *(uint32_t*)&h;
}

// -------------------- fp32 -> fp16 convert ---------------------------------
__global__ __launch_bounds__(256) void f2h(const float* __restrict__ s,
                                           __half* __restrict__ d) {
    int i = (blockIdx.x * 256 + threadIdx.x) * 4;
    float4 v = *(const float4*)(s + i);
    __half2* dp = (__half2*)(d + i);
    dp[0] = __floats2half2_rn(v.x, v.y);
    dp[1] = __floats2half2_rn(v.z, v.w);
}

// -------------------- fp16 tensor-core GEMM --------------------------------
// C[M,N] = A[M,K] @ B[K,N]; M=4096, N=K=1024. CTA 128x128, BK=32, 256 thr,
// 8 warps of 64x32, mma.m16n8k16, cp.async double-buffered smem.
template <bool OUTH>
__global__ __launch_bounds__(256, 2)
void gemm_h(const __half* __restrict__ A, const __half* __restrict__ Bw,
            float* __restrict__ Cf, __half* __restrict__ Chh)
{
    __shared__ __align__(16) __half As[2][128][40];   // pad 8 halves
    __shared__ __align__(16) __half Bs[2][32][136];   // pad 8 halves

    const int tid = threadIdx.x, lane = tid & 31, warp = tid >> 5;
    const int wm = warp >> 2, wn = warp & 3;
    const int rowBase = blockIdx.y * 128, colBase = blockIdx.x * 128;

    const int arow = tid >> 2, acq = tid & 3;   // A: rows arow, arow+64
    const int bnq  = tid & 15, bkr = tid >> 4;  // B: k-rows bkr, bkr+16

    float acc[4][4][4];
#pragma unroll
    for (int i = 0; i < 4; i++)
#pragma unroll
        for (int j = 0; j < 4; j++)
#pragma unroll
            for (int k = 0; k < 4; k++) acc[i][j][k] = 0.f;

    // prologue: tile 0 -> buf 0
    {
        const __half* Ag = A + (size_t)(rowBase + arow) * Hh + acq * 8;
        CPA16(su32(&As[0][arow][acq * 8]), Ag);
        CPA16(su32(&As[0][arow + 64][acq * 8]), Ag + (size_t)64 * Hh);
        const __half* Bg = Bw + (size_t)bkr * Hh + colBase + bnq * 8;
        CPA16(su32(&Bs[0][bkr][bnq * 8]), Bg);
        CPA16(su32(&Bs[0][bkr + 16][bnq * 8]), Bg + (size_t)16 * Hh);
        CPCOMMIT();
    }
    CPWAIT0();
    __syncthreads();

    for (int t = 0; t < 32; t++) {
        const int buf = t & 1;
        if (t < 31) {
            const int k0 = (t + 1) * 32;
            const __half* Ag = A + (size_t)(rowBase + arow) * Hh + k0 + acq * 8;
            CPA16(su32(&As[buf ^ 1][arow][acq * 8]), Ag);
            CPA16(su32(&As[buf ^ 1][arow + 64][acq * 8]), Ag + (size_t)64 * Hh);
            const __half* Bg = Bw + (size_t)(k0 + bkr) * Hh + colBase + bnq * 8;
            CPA16(su32(&Bs[buf ^ 1][bkr][bnq * 8]), Bg);
            CPA16(su32(&Bs[buf ^ 1][bkr + 16][bnq * 8]), Bg + (size_t)16 * Hh);
            CPCOMMIT();
        }
#pragma unroll
        for (int ks = 0; ks < 2; ks++) {
            uint32_t a[4][4], b[4][2];
#pragma unroll
            for (int mf = 0; mf < 4; mf++)
                ldm_x4(su32(&As[buf][wm * 64 + mf * 16 + (lane & 15)]
                                     [ks * 16 + ((lane >> 4) << 3)]),
                       a[mf][0], a[mf][1], a[mf][2], a[mf][3]);
            const int m = lane >> 3;
#pragma unroll
            for (int g = 0; g < 2; g++) {
                uint32_t addr = su32(&Bs[buf][ks * 16 + ((m & 1) << 3) + (lane & 7)]
                                             [wn * 32 + g * 16 + ((m >> 1) << 3)]);
                ldm_x4t(addr, b[2 * g][0], b[2 * g][1], b[2 * g + 1][0], b[2 * g + 1][1]);
            }
#pragma unroll
            for (int mf = 0; mf < 4; mf++)
#pragma unroll
                for (int nf = 0; nf < 4; nf++)
                    mma16816(acc[mf][nf], a[mf], b[nf]);
        }
        CPWAIT0();
        __syncthreads();
    }

    // epilogue
#pragma unroll
    for (int mf = 0; mf < 4; mf++) {
        const int r0 = rowBase + wm * 64 + mf * 16 + (lane >> 2);
#pragma unroll
        for (int nf = 0; nf < 4; nf++) {
            const int c = colBase + wn * 32 + nf * 8 + ((lane & 3) << 1);
            if (OUTH) {
                *(__half2*)&Chh[(size_t)r0 * Hh + c] =
                    __floats2half2_rn(acc[mf][nf][0], acc[mf][nf][1]);
                *(__half2*)&Chh[(size_t)(r0 + 8) * Hh + c] =
                    __floats2half2_rn(acc[mf][nf][2], acc[mf][nf][3]);
            } else {
                *(float2*)&Cf[(size_t)r0 * Hh + c] =
                    make_float2(acc[mf][nf][0], acc[mf][nf][1]);
                *(float2*)&Cf[(size_t)(r0 + 8) * Hh + c] =
                    make_float2(acc[mf][nf][2], acc[mf][nf][3]);
            }
        }
    }
}

// -------------------- fp16 flash attention ---------------------------------
// CTA: 64 q-rows x (head,batch). 128 thr = 4 warps, each warp owns 16 q-rows.
// Q resident in A-fragments; K via non-trans ldmatrix ([kv][d] = [n][k]);
// V via trans ldmatrix; P stays in registers (C-frag -> A-frag pack).
__global__ __launch_bounds__(128, 3)
void attn_h(const __half* __restrict__ Qh, const __half* __restrict__ Kh,
            const __half* __restrict__ Vh, const int* __restrict__ mask,
            __half* __restrict__ Ch)
{
    __shared__ __align__(16) __half Ks[2][64][72];
    __shared__ __align__(16) __half Vs[2][64][72];
    __shared__ float Ms[2][64];

    const int tid = threadIdx.x, lane = tid & 31, warp = tid >> 5;
    const int qt = blockIdx.x, h = blockIdx.y, b = blockIdx.z;
    const int qbase = qt * 64;

    const __half* Qg = Qh + (size_t)(b * Ss + qbase) * Hh + h * HDd;
    const __half* Kg = Kh + (size_t)(b * Ss) * Hh + h * HDd;
    const __half* Vg = Vh + (size_t)(b * Ss) * Hh + h * HDd;
    const int* mrw = mask + b * Ss;

    const int lrow = tid >> 3, lcq = tid & 7;

    // stage Q into Ks[1] (plain stores)
#pragma unroll
    for (int i = 0; i < 4; i++)
        *(uint4*)&Ks[1][lrow + 16 * i][lcq * 8] =
            *(const uint4*)(Qg + (size_t)(lrow + 16 * i) * Hh + lcq * 8);

    // prologue: async K/V tile 0 -> buf 0 + mask tile 0
#pragma unroll
    for (int i = 0; i < 4; i++) {
        CPA16(su32(&Ks[0][lrow + 16 * i][lcq * 8]),
              Kg + (size_t)(lrow + 16 * i) * Hh + lcq * 8);
        CPA16(su32(&Vs[0][lrow + 16 * i][lcq * 8]),
              Vg + (size_t)(lrow + 16 * i) * Hh + lcq * 8);
    }
    CPCOMMIT();
    if (tid < 64) Ms[0][tid] = (mrw[tid] == 0) ? -CUDART_INF_F : 0.f;
    __syncthreads();                       // Q staged & visible

    uint32_t qa[4][4];
#pragma unroll
    for (int kf = 0; kf < 4; kf++)
        ldm_x4(su32(&Ks[1][warp * 16 + (lane & 15)][kf * 16 + ((lane >> 4) << 3)]),
               qa[kf][0], qa[kf][1], qa[kf][2], qa[kf][3]);
    CPWAIT0();
    __syncthreads();                       // Ks[1] free + tile0 landed

    float o[8][4];
#pragma unroll
    for (int i = 0; i < 8; i++)
#pragma unroll
        for (int j = 0; j < 4; j++) o[i][j] = 0.f;
    float mprev[2] = {-1e30f, -1e30f};
    float lsum[2]  = {0.f, 0.f};

    for (int kt = 0; kt < Ss / 64; kt++) {
        const int buf = kt & 1;
        if (kt < Ss / 64 - 1) {
            const __half* Kg2 = Kg + (size_t)((kt + 1) * 64) * Hh;
            const __half* Vg2 = Vg + (size_t)((kt + 1) * 64) * Hh;
#pragma unroll
            for (int i = 0; i < 4; i++) {
                CPA16(su32(&Ks[buf ^ 1][lrow + 16 * i][lcq * 8]),
                      Kg2 + (size_t)(lrow + 16 * i) * Hh + lcq * 8);
                CPA16(su32(&Vs[buf ^ 1][lrow + 16 * i][lcq * 8]),
                      Vg2 + (size_t)(lrow + 16 * i) * Hh + lcq * 8);
            }
            CPCOMMIT();
            if (tid < 64)
                Ms[buf ^ 1][tid] = (mrw[(kt + 1) * 64 + tid] == 0) ? -CUDART_INF_F : 0.f;
        }

        // ---- S = Q @ K^T ----
        float s[8][4];
#pragma unroll
        for (int i = 0; i < 8; i++)
#pragma unroll
            for (int j = 0; j < 4; j++) s[i][j] = 0.f;

        const int m = lane >> 3;
#pragma unroll
        for (int kf = 0; kf < 4; kf++) {
            uint32_t kb[8][2];
#pragma unroll
            for (int g = 0; g < 4; g++) {
                uint32_t addr = su32(&Ks[buf][g * 16 + ((m >> 1) << 3) + (lane & 7)]
                                             [kf * 16 + ((m & 1) << 3)]);
                ldm_x4(addr, kb[2 * g][0], kb[2 * g][1], kb[2 * g + 1][0], kb[2 * g + 1][1]);
            }
#pragma unroll
            for (int nf = 0; nf < 8; nf++)
                mma16816(s[nf], qa[kf], kb[nf]);
        }

        // ---- scale, clip, mask, online softmax ----
        float es[2];
#pragma unroll
        for (int r = 0; r < 2; r++) {
            float mx = -CUDART_INF_F;
#pragma unroll
            for (int nf = 0; nf < 8; nf++) {
                const int c0 = nf * 8 + ((lane & 3) << 1);
                float v0 = fminf(fmaxf(s[nf][2 * r]     * 0.125f, -10000.f), 10000.f) + Ms[buf][c0];
                float v1 = fminf(fmaxf(s[nf][2 * r + 1] * 0.125f, -10000.f), 10000.f) + Ms[buf][c0 + 1];
                s[nf][2 * r] = v0; s[nf][2 * r + 1] = v1;
                mx = fmaxf(mx, fmaxf(v0, v1));
            }
            mx = fmaxf(mx, __shfl_xor_sync(0xffffffffu, mx, 1));
            mx = fmaxf(mx, __shfl_xor_sync(0xffffffffu, mx, 2));
            const float mn = fmaxf(mprev[r], mx);
            es[r] = __expf(mprev[r] - mn);
            mprev[r] = mn;
            float sum = 0.f;
#pragma unroll
            for (int nf = 0; nf < 8; nf++) {
                float p0 = __expf(s[nf][2 * r]     - mn);
                float p1 = __expf(s[nf][2 * r + 1] - mn);
                s[nf][2 * r] = p0; s[nf][2 * r + 1] = p1;
                sum += p0 + p1;
            }
            sum += __shfl_xor_sync(0xffffffffu, sum, 1);
            sum += __shfl_xor_sync(0xffffffffu, sum, 2);
            lsum[r] = lsum[r] * es[r] + sum;
        }
#pragma unroll
        for (int nf = 0; nf < 8; nf++) {
            o[nf][0] *= es[0]; o[nf][1] *= es[0];
            o[nf][2] *= es[1]; o[nf][3] *= es[1];
        }

        // ---- O += P @ V ----
#pragma unroll
        for (int j = 0; j < 4; j++) {           // kv k16 chunks
            uint32_t pa[4];
            pa[0] = packh2(s[2 * j][0],     s[2 * j][1]);
            pa[1] = packh2(s[2 * j][2],     s[2 * j][3]);
            pa[2] = packh2(s[2 * j + 1][0], s[2 * j + 1][1]);
            pa[3] = packh2(s[2 * j + 1][2], s[2 * j + 1][3]);
#pragma unroll
            for (int g = 0; g < 4; g++) {       // d n16 groups
                uint32_t vb[4];
                uint32_t addr = su32(&Vs[buf][j * 16 + ((m & 1) << 3) + (lane & 7)]
                                             [g * 16 + ((m >> 1) << 3)]);
                ldm_x4t(addr, vb[0], vb[1], vb[2], vb[3]);
                mma16816(o[2 * g],     pa, &vb[0]);
                mma16816(o[2 * g + 1], pa, &vb[2]);
            }
        }
        CPWAIT0();
        __syncthreads();
    }

    // ---- epilogue ----
    const float i0 = 1.f / lsum[0];
    const float i1 = 1.f / lsum[1];
    const int r0 = qbase + warp * 16 + (lane >> 2);
#pragma unroll
    for (int nf = 0; nf < 8; nf++) {
        const int c = h * HDd + nf * 8 + ((lane & 3) << 1);
        *(__half2*)&Ch[(size_t)(b * Ss + r0) * Hh + c] =
            __floats2half2_rn(o[nf][0] * i0, o[nf][1] * i0);
        *(__half2*)&Ch[(size_t)(b * Ss + r0 + 8) * Hh + c] =
            __floats2half2_rn(o[nf][2] * i1, o[nf][3] * i1);
    }
}

// ---------------------------------------------------------------------------
extern "C" void kernel_launch(void* const* d_in, const int* in_sizes, int n_in,
                              void* d_out, int out_size)
{
    const float* X    = (const float*)d_in[0];
    const int*   mask = (const int*)  d_in[1];
    const float* WQ   = (const float*)d_in[2];
    const float* WK   = (const float*)d_in[3];
    const float* WV   = (const float*)d_in[4];
    const float* WO   = (const float*)d_in[5];
    float* out = (float*)d_out;

    __half *pXh, *pWh, *pQh, *pKh, *pVh, *pCh;
    cudaGetSymbolAddress((void**)&pXh, g_Xh);
    cudaGetSymbolAddress((void**)&pWh, g_Wh);
    cudaGetSymbolAddress((void**)&pQh, g_Qh);
    cudaGetSymbolAddress((void**)&pKh, g_Kh);
    cudaGetSymbolAddress((void**)&pVh, g_Vh);
    cudaGetSymbolAddress((void**)&pCh, g_Ch);

    f2h<<<(Mm * Hh) / 1024, 256>>>(X,  pXh);
    f2h<<<(Hh * Hh) / 1024, 256>>>(WQ, pWh + 0 * (size_t)Hh * Hh);
    f2h<<<(Hh * Hh) / 1024, 256>>>(WK, pWh + 1 * (size_t)Hh * Hh);
    f2h<<<(Hh * Hh) / 1024, 256>>>(WV, pWh + 2 * (size_t)Hh * Hh);
    f2h<<<(Hh * Hh) / 1024, 256>>>(WO, pWh + 3 * (size_t)Hh * Hh);

    dim3 gg(Hh / 128, Mm / 128);   // (8, 32)
    gemm_h<true ><<<gg, 256>>>(pXh, pWh + 0 * (size_t)Hh * Hh, nullptr, pQh);
    gemm_h<true ><<<gg, 256>>>(pXh, pWh + 1 * (size_t)Hh * Hh, nullptr, pKh);
    gemm_h<true ><<<gg, 256>>>(pXh, pWh + 2 * (size_t)Hh * Hh, nullptr, pVh);

    attn_h<<<dim3(Ss / 64, NHh, Bb), 128>>>(pQh, pKh, pVh, mask, pCh);

    gemm_h<false><<<gg, 256>>>(pCh, pWh + 3 * (size_t)Hh * Hh, out, nullptr);

    (void)in_sizes; (void)n_in; (void)out_size;
}